// round 1
// baseline (speedup 1.0000x reference)
#include <cuda_runtime.h>

#define NB 256
#define NT 1024
#define NV 5000
#define ND 100
#define NH 64
#define NC 2

// Scratch: EW = E @ W + b, [V, H]. 1.28 MB -> fully L2-resident.
__device__ float g_EWb[NV * NH];

// ---------------------------------------------------------------------------
// Kernel A: EWb[v][j] = sum_d E[v][d] * W[d][j] + b[j]
// 4 vocab rows per 256-thread block.
// ---------------------------------------------------------------------------
__global__ void ew_kernel(const float* __restrict__ E,
                          const float* __restrict__ W,
                          const float* __restrict__ bias) {
    int v = blockIdx.x * 4 + (threadIdx.x >> 6);
    int j = threadIdx.x & 63;
    if (v >= NV) return;
    float acc = bias[j];
    const float* e = E + v * ND;
    #pragma unroll 4
    for (int d = 0; d < ND; d++)
        acc = fmaf(e[d], W[d * NH + j], acc);
    g_EWb[v * NH + j] = acc;
}

typedef unsigned long long u64;

__device__ __forceinline__ u64 ffma2(u64 a, u64 b, u64 c) {
    u64 d;
    asm("fma.rn.f32x2 %0, %1, %2, %3;" : "=l"(d) : "l"(a), "l"(b), "l"(c));
    return d;
}
__device__ __forceinline__ u64 fadd2(u64 a, u64 b) {
    u64 d;
    asm("add.rn.f32x2 %0, %1, %2;" : "=l"(d) : "l"(a), "l"(b));
    return d;
}
__device__ __forceinline__ u64 pk2(float x, float y) {
    u64 r;
    asm("mov.b64 %0, {%1, %2};" : "=l"(r) : "f"(x), "f"(y));
    return r;
}
__device__ __forceinline__ void upk2(u64 v, float& x, float& y) {
    asm("mov.b64 {%0, %1}, %2;" : "=f"(x), "=f"(y) : "l"(v));
}

// ---------------------------------------------------------------------------
// Kernel B: masked tanh RNN over T=1024 steps + mean-pool + dense + sigmoid.
// One warp per batch row. Lane l owns outputs (2l, 2l+1) as an f32x2 pair.
// U[:, 2l:2l+2] lives in 64 packed registers. h is kept in shared memory,
// DUPLICATED (h[k],h[k] adjacent) so LDS.128 yields two FFMA2 multiplicands.
// 128-thread blocks (4 rows) -> warps land on SMSP 0..3, one warp per SMSP.
// ---------------------------------------------------------------------------
__global__ void __launch_bounds__(128) rnn_kernel(
    const int* __restrict__ tokens,
    const float* __restrict__ U,
    const float* __restrict__ Wd,
    const float* __restrict__ bd,
    float* __restrict__ out)
{
    __shared__ __align__(16) float hdup[4][2 * NH];
    const int wid = threadIdx.x >> 5;
    const int l   = threadIdx.x & 31;
    const int b   = blockIdx.x * 4 + wid;

    // Load U columns (2l, 2l+1), packed. 64 x 64-bit = 128 registers.
    u64 Upk[NH];
    #pragma unroll
    for (int k = 0; k < NH; k++) {
        float2 u = *reinterpret_cast<const float2*>(U + k * NH + 2 * l);
        Upk[k] = pk2(u.x, u.y);
    }

    // h = 0
    reinterpret_cast<float4*>(hdup[wid])[l] = make_float4(0.f, 0.f, 0.f, 0.f);
    __syncwarp();

    const int* trow = tokens + b * NT;
    float hx = 0.f, hy = 0.f, sx = 0.f, sy = 0.f;

    // Software pipeline: tokens 3 ahead, EW rows 2 ahead (L2 latency ~234cyc).
    int tok0 = trow[0];
    int tok1 = trow[1];
    int tok2 = trow[2];
    float2 ew0 = *reinterpret_cast<const float2*>(g_EWb + tok0 * NH + 2 * l);
    float2 ew1 = *reinterpret_cast<const float2*>(g_EWb + tok1 * NH + 2 * l);

    for (int t = 0; t < NT; t++) {
        int t3 = (t + 3 < NT) ? (t + 3) : (NT - 1);
        int tok3 = trow[t3];
        float2 ew2 = *reinterpret_cast<const float2*>(g_EWb + tok2 * NH + 2 * l);

        // acc = EW[tok] (+b folded) + h @ U   (packed pair for j = 2l, 2l+1)
        u64 a0 = pk2(ew0.x, ew0.y);
        u64 a1 = 0ull, a2 = 0ull, a3 = 0ull;
        const ulonglong2* hp = reinterpret_cast<const ulonglong2*>(hdup[wid]);
        #pragma unroll
        for (int m = 0; m < NH / 2; m++) {
            ulonglong2 hv = hp[m];   // (h[2m],h[2m]) , (h[2m+1],h[2m+1])
            if (m & 1) {
                a2 = ffma2(hv.x, Upk[2 * m],     a2);
                a3 = ffma2(hv.y, Upk[2 * m + 1], a3);
            } else {
                a0 = ffma2(hv.x, Upk[2 * m],     a0);
                a1 = ffma2(hv.y, Upk[2 * m + 1], a1);
            }
        }
        u64 a = fadd2(fadd2(a0, a2), fadd2(a1, a3));
        float ax, ay;
        upk2(a, ax, ay);
        float nx = tanhf(ax);
        float ny = tanhf(ay);

        // Masked recurrence: token 0 carries previous state. Uniform per warp.
        if (tok0 != 0) { hx = nx; hy = ny; }
        sx += hx;
        sy += hy;

        // Publish duplicated h for next step.
        reinterpret_cast<float4*>(hdup[wid])[l] = make_float4(hx, hx, hy, hy);
        __syncwarp();

        tok0 = tok1; tok1 = tok2; tok2 = tok3;
        ew0 = ew1;  ew1 = ew2;
    }

    // Epilogue: mean pool -> dense (H=64 -> C=2) -> sigmoid, warp-reduced.
    float px = sx * (1.0f / NT);
    float py = sy * (1.0f / NT);
    float c0 = px * Wd[(2 * l) * NC + 0] + py * Wd[(2 * l + 1) * NC + 0];
    float c1 = px * Wd[(2 * l) * NC + 1] + py * Wd[(2 * l + 1) * NC + 1];
    #pragma unroll
    for (int off = 16; off; off >>= 1) {
        c0 += __shfl_xor_sync(0xffffffffu, c0, off);
        c1 += __shfl_xor_sync(0xffffffffu, c1, off);
    }
    if (l == 0) {
        out[b * NC + 0] = 1.0f / (1.0f + expf(-(c0 + bd[0])));
        out[b * NC + 1] = 1.0f / (1.0f + expf(-(c1 + bd[1])));
    }
}

// ---------------------------------------------------------------------------
// Launch. Inputs (metadata order): tokens, E, W, U, b, Wd, bd. Output: [B, C] f32.
// ---------------------------------------------------------------------------
extern "C" void kernel_launch(void* const* d_in, const int* in_sizes, int n_in,
                              void* d_out, int out_size) {
    const int*   tokens = (const int*)  d_in[0];
    const float* E      = (const float*)d_in[1];
    const float* W      = (const float*)d_in[2];
    const float* U      = (const float*)d_in[3];
    const float* bias   = (const float*)d_in[4];
    const float* Wd     = (const float*)d_in[5];
    const float* bd     = (const float*)d_in[6];
    float* out = (float*)d_out;

    ew_kernel<<<(NV + 3) / 4, 256>>>(E, W, bias);
    rnn_kernel<<<NB / 4, 128>>>(tokens, U, Wd, bd, out);
}

// round 2
// speedup vs baseline: 1.0014x; 1.0014x over previous
#include <cuda_runtime.h>

#define NB 256
#define NT 1024
#define NV 5000
#define ND 100
#define NH 64
#define NC 2

// Scratch: EW = E @ W + b, [V, H]. 1.28 MB -> fully L2-resident.
__device__ float g_EWb[NV * NH];

// ---------------------------------------------------------------------------
// Kernel A: EWb[v][j] = sum_d E[v][d] * W[d][j] + b[j]
// ---------------------------------------------------------------------------
__global__ void ew_kernel(const float* __restrict__ E,
                          const float* __restrict__ W,
                          const float* __restrict__ bias) {
    int v = blockIdx.x * 4 + (threadIdx.x >> 6);
    int j = threadIdx.x & 63;
    if (v >= NV) return;
    float acc = bias[j];
    const float* e = E + v * ND;
    #pragma unroll 4
    for (int d = 0; d < ND; d++)
        acc = fmaf(e[d], W[d * NH + j], acc);
    g_EWb[v * NH + j] = acc;
}

typedef unsigned long long u64;

__device__ __forceinline__ u64 ffma2(u64 a, u64 b, u64 c) {
    u64 d;
    asm("fma.rn.f32x2 %0, %1, %2, %3;" : "=l"(d) : "l"(a), "l"(b), "l"(c));
    return d;
}
__device__ __forceinline__ u64 fadd2(u64 a, u64 b) {
    u64 d;
    asm("add.rn.f32x2 %0, %1, %2;" : "=l"(d) : "l"(a), "l"(b));
    return d;
}
__device__ __forceinline__ u64 pk2(float x, float y) {
    u64 r;
    asm("mov.b64 %0, {%1, %2};" : "=l"(r) : "f"(x), "f"(y));
    return r;
}
__device__ __forceinline__ void upk2(u64 v, float& x, float& y) {
    asm("mov.b64 {%0, %1}, %2;" : "=f"(x), "=f"(y) : "l"(v));
}
// HW tanh (MUFU.TANH, sm_75+): lat 16, single instruction, ~2^-11 error.
__device__ __forceinline__ float tanh_fast(float x) {
    float y;
    asm("tanh.approx.f32 %0, %1;" : "=f"(y) : "f"(x));
    return y;
}

// ---------------------------------------------------------------------------
// Kernel B: masked tanh RNN over T=1024 steps + mean-pool + dense + sigmoid.
// One warp per batch row. Lane l owns outputs (2l, 2l+1) as an f32x2 pair.
// U[:, 2l:2l+2] in 128 registers. h in shared, DUPLICATED so LDS.128 yields
// two ready FFMA2 multiplicands. 128-thread blocks -> 1 warp per SMSP.
// ---------------------------------------------------------------------------
__global__ void __launch_bounds__(128) rnn_kernel(
    const int* __restrict__ tokens,
    const float* __restrict__ U,
    const float* __restrict__ Wd,
    const float* __restrict__ bd,
    float* __restrict__ out)
{
    __shared__ __align__(16) float hdup[4][2 * NH];
    const int wid = threadIdx.x >> 5;
    const int l   = threadIdx.x & 31;
    const int b   = blockIdx.x * 4 + wid;

    u64 Upk[NH];
    #pragma unroll
    for (int k = 0; k < NH; k++) {
        float2 u = *reinterpret_cast<const float2*>(U + k * NH + 2 * l);
        Upk[k] = pk2(u.x, u.y);
    }

    reinterpret_cast<float4*>(hdup[wid])[l] = make_float4(0.f, 0.f, 0.f, 0.f);
    __syncwarp();

    const int* trow = tokens + b * NT;
    float hx = 0.f, hy = 0.f, sx = 0.f, sy = 0.f;

    // Pipeline: tokens 3 ahead, EW rows 2 ahead (L2 hit ~234cyc < 2 steps).
    int tok0 = trow[0];
    int tok1 = trow[1];
    int tok2 = trow[2];
    float2 ew0 = *reinterpret_cast<const float2*>(g_EWb + tok0 * NH + 2 * l);
    float2 ew1 = *reinterpret_cast<const float2*>(g_EWb + tok1 * NH + 2 * l);

    for (int t = 0; t < NT; t++) {
        int t3 = (t + 3 < NT) ? (t + 3) : (NT - 1);
        int tok3 = trow[t3];
        float2 ew2 = *reinterpret_cast<const float2*>(g_EWb + tok2 * NH + 2 * l);

        // acc = EW[tok] + h @ U  (packed pair for j = 2l, 2l+1)
        // 8 accumulators -> FFMA dep depth 8 (32 cyc) instead of 16.
        u64 A0 = pk2(ew0.x, ew0.y);
        u64 A1 = 0ull, A2 = 0ull, A3 = 0ull;
        u64 A4 = 0ull, A5 = 0ull, A6 = 0ull, A7 = 0ull;
        const ulonglong2* hp = reinterpret_cast<const ulonglong2*>(hdup[wid]);
        #pragma unroll
        for (int m = 0; m < NH / 2; m += 4) {
            ulonglong2 h0 = hp[m];
            ulonglong2 h1 = hp[m + 1];
            ulonglong2 h2 = hp[m + 2];
            ulonglong2 h3 = hp[m + 3];
            A0 = ffma2(h0.x, Upk[2 * m],     A0);
            A1 = ffma2(h0.y, Upk[2 * m + 1], A1);
            A2 = ffma2(h1.x, Upk[2 * m + 2], A2);
            A3 = ffma2(h1.y, Upk[2 * m + 3], A3);
            A4 = ffma2(h2.x, Upk[2 * m + 4], A4);
            A5 = ffma2(h2.y, Upk[2 * m + 5], A5);
            A6 = ffma2(h3.x, Upk[2 * m + 6], A6);
            A7 = ffma2(h3.y, Upk[2 * m + 7], A7);
        }
        u64 a = fadd2(fadd2(fadd2(A0, A1), fadd2(A2, A3)),
                      fadd2(fadd2(A4, A5), fadd2(A6, A7)));
        float ax, ay;
        upk2(a, ax, ay);
        float nx = tanh_fast(ax);
        float ny = tanh_fast(ay);

        // Masked recurrence: token 0 carries previous state (warp-uniform).
        if (tok0 != 0) { hx = nx; hy = ny; }
        sx += hx;
        sy += hy;

        reinterpret_cast<float4*>(hdup[wid])[l] = make_float4(hx, hx, hy, hy);
        __syncwarp();

        tok0 = tok1; tok1 = tok2; tok2 = tok3;
        ew0 = ew1;  ew1 = ew2;
    }

    // Epilogue: mean pool -> dense (H=64 -> C=2) -> sigmoid, warp-reduced.
    float px = sx * (1.0f / NT);
    float py = sy * (1.0f / NT);
    float c0 = px * Wd[(2 * l) * NC + 0] + py * Wd[(2 * l + 1) * NC + 0];
    float c1 = px * Wd[(2 * l) * NC + 1] + py * Wd[(2 * l + 1) * NC + 1];
    #pragma unroll
    for (int off = 16; off; off >>= 1) {
        c0 += __shfl_xor_sync(0xffffffffu, c0, off);
        c1 += __shfl_xor_sync(0xffffffffu, c1, off);
    }
    if (l == 0) {
        out[b * NC + 0] = 1.0f / (1.0f + expf(-(c0 + bd[0])));
        out[b * NC + 1] = 1.0f / (1.0f + expf(-(c1 + bd[1])));
    }
}

// ---------------------------------------------------------------------------
extern "C" void kernel_launch(void* const* d_in, const int* in_sizes, int n_in,
                              void* d_out, int out_size) {
    const int*   tokens = (const int*)  d_in[0];
    const float* E      = (const float*)d_in[1];
    const float* W      = (const float*)d_in[2];
    const float* U      = (const float*)d_in[3];
    const float* bias   = (const float*)d_in[4];
    const float* Wd     = (const float*)d_in[5];
    const float* bd     = (const float*)d_in[6];
    float* out = (float*)d_out;

    ew_kernel<<<(NV + 3) / 4, 256>>>(E, W, bias);
    rnn_kernel<<<NB / 4, 128>>>(tokens, U, Wd, bd, out);
}

// round 3
// speedup vs baseline: 1.9512x; 1.9485x over previous
#include <cuda_runtime.h>

#define NB 256
#define NT 1024
#define NV 5000
#define ND 100
#define NH 64
#define NC 2

// Scratch: EW = E @ W + b, [V, H]. 1.28 MB -> fully L2-resident.
__device__ float g_EWb[NV * NH];

// ---------------------------------------------------------------------------
// Kernel A: EWb[v][j] = sum_d E[v][d] * W[d][j] + b[j]
// ---------------------------------------------------------------------------
__global__ void ew_kernel(const float* __restrict__ E,
                          const float* __restrict__ W,
                          const float* __restrict__ bias) {
    int v = blockIdx.x * 4 + (threadIdx.x >> 6);
    int j = threadIdx.x & 63;
    if (v >= NV) return;
    float acc = bias[j];
    const float* e = E + v * ND;
    #pragma unroll 4
    for (int d = 0; d < ND; d++)
        acc = fmaf(e[d], W[d * NH + j], acc);
    g_EWb[v * NH + j] = acc;
}

// HW tanh (MUFU.TANH): lat 16, single instruction, ~2^-11 error.
__device__ __forceinline__ float tanh_fast(float x) {
    float y;
    asm("tanh.approx.f32 %0, %1;" : "=f"(y) : "f"(x));
    return y;
}

// ---------------------------------------------------------------------------
// Kernel B: masked tanh RNN, T=1024 steps + mean-pool + dense + sigmoid.
// ONE BLOCK (64 threads = 2 warps) PER BATCH ROW. Thread owns output
// j = threadIdx.x; U[:,j] lives in 64 registers. h exchanged through
// ping-pong shared buffers with a single __syncthreads per step (the BAR
// also drains the STS). Scalar FFMA only: no wide-operand RF conflicts.
// ---------------------------------------------------------------------------
__global__ void __launch_bounds__(64) rnn_kernel(
    const int* __restrict__ tokens,
    const float* __restrict__ U,
    const float* __restrict__ Wd,
    const float* __restrict__ bd,
    float* __restrict__ out)
{
    __shared__ __align__(16) float hbuf[2][NH];
    __shared__ float red[2][2];
    const int j = threadIdx.x;          // owned output index (0..63)
    const int w = threadIdx.x >> 5;     // warp in block
    const int l = threadIdx.x & 31;
    const int b = blockIdx.x;

    // U column j in registers.
    float Ucol[NH];
    #pragma unroll
    for (int k = 0; k < NH; k++)
        Ucol[k] = U[k * NH + j];

    hbuf[0][j] = 0.f;
    __syncthreads();

    const int* trow = tokens + b * NT;
    float h = 0.f, s = 0.f;

    // Pipeline: tokens 3 ahead, EW rows 2 ahead (>= L2 latency at ~200cyc/step).
    int tok0 = trow[0];
    int tok1 = trow[1];
    int tok2 = trow[2];
    float ew0 = g_EWb[tok0 * NH + j];
    float ew1 = g_EWb[tok1 * NH + j];

    #pragma unroll 2
    for (int t = 0; t < NT; t++) {
        int t3 = (t + 3 < NT) ? (t + 3) : (NT - 1);
        int tok3 = trow[t3];
        float ew2 = g_EWb[tok2 * NH + j];

        // a = EW[tok][j] + sum_k h[k] * U[k][j]; 8 accumulators, 16x LDS.128.
        const float4* hp = reinterpret_cast<const float4*>(hbuf[t & 1]);
        float a0 = ew0, a1 = 0.f, a2 = 0.f, a3 = 0.f;
        float a4 = 0.f, a5 = 0.f, a6 = 0.f, a7 = 0.f;
        #pragma unroll
        for (int m = 0; m < NH / 4; m += 2) {
            float4 h0 = hp[m];
            float4 h1 = hp[m + 1];
            a0 = fmaf(h0.x, Ucol[4 * m + 0], a0);
            a1 = fmaf(h0.y, Ucol[4 * m + 1], a1);
            a2 = fmaf(h0.z, Ucol[4 * m + 2], a2);
            a3 = fmaf(h0.w, Ucol[4 * m + 3], a3);
            a4 = fmaf(h1.x, Ucol[4 * m + 4], a4);
            a5 = fmaf(h1.y, Ucol[4 * m + 5], a5);
            a6 = fmaf(h1.z, Ucol[4 * m + 6], a6);
            a7 = fmaf(h1.w, Ucol[4 * m + 7], a7);
        }
        float a = ((a0 + a1) + (a2 + a3)) + ((a4 + a5) + (a6 + a7));
        float hn = tanh_fast(a);

        // Masked recurrence: token 0 carries previous state (block-uniform).
        if (tok0 != 0) h = hn;
        s += h;

        // Publish into the *other* buffer; one barrier per step.
        hbuf[(t & 1) ^ 1][j] = h;
        __syncthreads();

        tok0 = tok1; tok1 = tok2; tok2 = tok3;
        ew0 = ew1;  ew1 = ew2;
    }

    // Epilogue: mean pool -> dense (64 -> 2) -> sigmoid.
    float p  = s * (1.0f / NT);
    float c0 = p * Wd[j * NC + 0];
    float c1 = p * Wd[j * NC + 1];
    #pragma unroll
    for (int off = 16; off; off >>= 1) {
        c0 += __shfl_xor_sync(0xffffffffu, c0, off);
        c1 += __shfl_xor_sync(0xffffffffu, c1, off);
    }
    if (l == 0) { red[w][0] = c0; red[w][1] = c1; }
    __syncthreads();
    if (threadIdx.x == 0) {
        float C0 = red[0][0] + red[1][0] + bd[0];
        float C1 = red[0][1] + red[1][1] + bd[1];
        out[b * NC + 0] = 1.0f / (1.0f + expf(-C0));
        out[b * NC + 1] = 1.0f / (1.0f + expf(-C1));
    }
}

// ---------------------------------------------------------------------------
extern "C" void kernel_launch(void* const* d_in, const int* in_sizes, int n_in,
                              void* d_out, int out_size) {
    const int*   tokens = (const int*)  d_in[0];
    const float* E      = (const float*)d_in[1];
    const float* W      = (const float*)d_in[2];
    const float* U      = (const float*)d_in[3];
    const float* bias   = (const float*)d_in[4];
    const float* Wd     = (const float*)d_in[5];
    const float* bd     = (const float*)d_in[6];
    float* out = (float*)d_out;

    ew_kernel<<<(NV + 3) / 4, 256>>>(E, W, bias);
    rnn_kernel<<<NB, 64>>>(tokens, U, Wd, bd, out);
}

// round 4
// speedup vs baseline: 2.3601x; 1.2096x over previous
#include <cuda_runtime.h>

#define NB 256
#define NT 1024
#define NV 5000
#define ND 100
#define NH 64
#define NC 2

// Scratch: EW = E @ W + b, [V, H]. 1.28 MB -> fully L2-resident.
__device__ float g_EWb[NV * NH];

// ---------------------------------------------------------------------------
// Kernel A: EWb[v][j] = sum_d E[v][d] * W[d][j] + b[j]
// ---------------------------------------------------------------------------
__global__ void ew_kernel(const float* __restrict__ E,
                          const float* __restrict__ W,
                          const float* __restrict__ bias) {
    int v = blockIdx.x * 4 + (threadIdx.x >> 6);
    int j = threadIdx.x & 63;
    if (v >= NV) return;
    float acc = bias[j];
    const float* e = E + v * ND;
    #pragma unroll 4
    for (int d = 0; d < ND; d++)
        acc = fmaf(e[d], W[d * NH + j], acc);
    g_EWb[v * NH + j] = acc;
}

// HW tanh (MUFU.TANH): lat 16, single instruction, ~2^-11 error.
__device__ __forceinline__ float tanh_fast(float x) {
    float y;
    asm("tanh.approx.f32 %0, %1;" : "=f"(y) : "f"(x));
    return y;
}

// ---------------------------------------------------------------------------
// Kernel B: masked tanh RNN, T=1024 steps + mean-pool + dense + sigmoid.
// ONE BLOCK (128 threads = 4 warps) PER BATCH ROW, K-SPLIT BY 2 IN-WARP:
// lanes (l, l+16) of warp w both own output j = 16w + (l&15); lane's K-half
// is l>>4. Per thread: 32 FFMA + 8 LDS.128; partials merge with ONE
// shfl.bfly(16) (same warp), so still one __syncthreads per step.
// Both partner lanes redundantly compute tanh/mask; l<16 publishes h.
// ---------------------------------------------------------------------------
__global__ void __launch_bounds__(128) rnn_kernel(
    const int* __restrict__ tokens,
    const float* __restrict__ U,
    const float* __restrict__ Wd,
    const float* __restrict__ bd,
    float* __restrict__ out)
{
    __shared__ __align__(16) float hbuf[2][NH];
    __shared__ float red[4][2];
    const int w     = threadIdx.x >> 5;
    const int l     = threadIdx.x & 31;
    const int jloc  = l & 15;
    const int j     = w * 16 + jloc;     // owned output index
    const int kbase = (l >> 4) * 32;     // this lane's K-half
    const int b     = blockIdx.x;

    // U[kbase..kbase+31][j] in 32 registers.
    float Ucol[NH / 2];
    #pragma unroll
    for (int k = 0; k < NH / 2; k++)
        Ucol[k] = U[(kbase + k) * NH + j];

    if (threadIdx.x < NH) hbuf[0][threadIdx.x] = 0.f;
    __syncthreads();

    const int* trow = tokens + b * NT;
    float h = 0.f, s = 0.f;

    // Pipeline: tokens 3 ahead, EW rows 2 ahead (2 steps >= L2 ~234cyc).
    int tok0 = trow[0];
    int tok1 = trow[1];
    int tok2 = trow[2];
    float ew0 = g_EWb[tok0 * NH + j];
    float ew1 = g_EWb[tok1 * NH + j];

    #pragma unroll 2
    for (int t = 0; t < NT; t++) {
        int t3 = (t + 3 < NT) ? (t + 3) : (NT - 1);
        int tok3 = trow[t3];
        float ew2 = g_EWb[tok2 * NH + j];

        // Partial dot: sum_{k in half} h[k] * U[k][j].  8 broadcast LDS.128.
        const float4* hp = reinterpret_cast<const float4*>(hbuf[t & 1] + kbase);
        float a0 = 0.f, a1 = 0.f, a2 = 0.f, a3 = 0.f;
        float a4 = 0.f, a5 = 0.f, a6 = 0.f, a7 = 0.f;
        #pragma unroll
        for (int m = 0; m < 8; m += 2) {
            float4 h0 = hp[m];
            float4 h1 = hp[m + 1];
            a0 = fmaf(h0.x, Ucol[4 * m + 0], a0);
            a1 = fmaf(h0.y, Ucol[4 * m + 1], a1);
            a2 = fmaf(h0.z, Ucol[4 * m + 2], a2);
            a3 = fmaf(h0.w, Ucol[4 * m + 3], a3);
            a4 = fmaf(h1.x, Ucol[4 * m + 4], a4);
            a5 = fmaf(h1.y, Ucol[4 * m + 5], a5);
            a6 = fmaf(h1.z, Ucol[4 * m + 6], a6);
            a7 = fmaf(h1.w, Ucol[4 * m + 7], a7);
        }
        float p = ((a0 + a1) + (a2 + a3)) + ((a4 + a5) + (a6 + a7));
        // Merge K-halves: partner lane is l^16, same warp.
        float a = p + __shfl_xor_sync(0xffffffffu, p, 16) + ew0;
        float hn = tanh_fast(a);

        // Masked recurrence: token 0 carries previous state (block-uniform).
        if (tok0 != 0) h = hn;
        s += h;

        // Publish into the other buffer (one writer per output).
        if (l < 16) hbuf[(t & 1) ^ 1][j] = h;
        __syncthreads();

        tok0 = tok1; tok1 = tok2; tok2 = tok3;
        ew0 = ew1;  ew1 = ew2;
    }

    // Epilogue: mean pool -> dense (64 -> 2) -> sigmoid.
    // Each output j is duplicated in 2 lanes; count only l<16.
    float p  = s * (1.0f / NT);
    float c0 = (l < 16) ? p * Wd[j * NC + 0] : 0.f;
    float c1 = (l < 16) ? p * Wd[j * NC + 1] : 0.f;
    #pragma unroll
    for (int off = 16; off; off >>= 1) {
        c0 += __shfl_xor_sync(0xffffffffu, c0, off);
        c1 += __shfl_xor_sync(0xffffffffu, c1, off);
    }
    if (l == 0) { red[w][0] = c0; red[w][1] = c1; }
    __syncthreads();
    if (threadIdx.x == 0) {
        float C0 = red[0][0] + red[1][0] + red[2][0] + red[3][0] + bd[0];
        float C1 = red[0][1] + red[1][1] + red[2][1] + red[3][1] + bd[1];
        out[b * NC + 0] = 1.0f / (1.0f + expf(-C0));
        out[b * NC + 1] = 1.0f / (1.0f + expf(-C1));
    }
}

// ---------------------------------------------------------------------------
extern "C" void kernel_launch(void* const* d_in, const int* in_sizes, int n_in,
                              void* d_out, int out_size) {
    const int*   tokens = (const int*)  d_in[0];
    const float* E      = (const float*)d_in[1];
    const float* W      = (const float*)d_in[2];
    const float* U      = (const float*)d_in[3];
    const float* bias   = (const float*)d_in[4];
    const float* Wd     = (const float*)d_in[5];
    const float* bd     = (const float*)d_in[6];
    float* out = (float*)d_out;

    ew_kernel<<<(NV + 3) / 4, 256>>>(E, W, bias);
    rnn_kernel<<<NB, 128>>>(tokens, U, Wd, bd, out);
}